// round 12
// baseline (speedup 1.0000x reference)
#include <cuda_runtime.h>
#include <cstdint>

#define BB      48
#define NKC     800
#define NMBON   20
#define NFBN    60
#define NDAN    20
#define NREC    100
#define TT      121
#define NSTEP   120
#define W_MAXC  0.05f

#define NTHREADS 512
#define NCTA     (BB * 2)

__device__ float g_rkcT[(long)BB * TT * NKC];

// ---------------------------------------------------------------------------
// Transpose r_kc [B, NKC, T] -> g_rkcT [B, T, NKC]
// ---------------------------------------------------------------------------
__global__ void transpose_kernel(const float* __restrict__ rkc) {
    __shared__ float tile[32][33];
    const int bz = blockIdx.z;
    const int kt = blockIdx.y;
    const int tt = blockIdx.x;
    const int tx = threadIdx.x, ty = threadIdx.y;

    int k = kt * 32 + ty;
    int t = tt * 32 + tx;
    if (t < TT)
        tile[ty][tx] = rkc[((long)bz * NKC + k) * TT + t];
    __syncthreads();
    int t2 = tt * 32 + ty;
    int k2 = kt * 32 + tx;
    if (t2 < TT)
        g_rkcT[((long)bz * TT + t2) * NKC + k2] = tile[tx][ty];
}

// ---------------------------------------------------------------------------
// R11 (279us) + (a) EARLY partial-send exchange: each owner warp ships its 5
// I_mbon partials to the peer pre-bar1 (mbar count 14); peer waiters sum 7
// slots after wait. (b) readout moved to warp 15 lane 24, pre-bar1.
// Cluster of 2 CTAs per batch (m-split), 512 threads.
// ---------------------------------------------------------------------------
// smem floats: mbar 4 | imb 140 (2 x 7slots x 10rows) | WrM 10000 | rkc4 3200 |
//   r 200 | bias 100 | ifbn 128 | red 80 | rdan 20 | rbdan 20 | wro 20 | wext 120
#define SM_FLOATS (4 + 140 + 10000 + 3200 + 200 + 100 + 128 + 80 + 20 + 20 + 20 + 120)

__global__ __launch_bounds__(NTHREADS, 1) __cluster_dims__(2, 1, 1)
void rnn_kernel(
    const float* __restrict__ r_ext,
    const float* __restrict__ time_arr,
    const float* __restrict__ W_kc0,
    const float* __restrict__ wt0,
    const float* __restrict__ W_recur,
    const float* __restrict__ W_readout,
    const float* __restrict__ bias,
    const float* __restrict__ W_ext,
    float* __restrict__ out)
{
    extern __shared__ float sm[];
    float* mbar_f  = sm;                  // 4
    float* imb     = sm + 4;              // 2 x 70 (per-warp partials from peer)
    float* WrM     = sm + 144;            // 100 x 100 row-major
    float* rkc4    = sm + 10144;          // 4 x 800 ring
    float* r_s     = sm + 13344;          // 2 x 100
    float* bias_s  = sm + 13544;          // 100
    float* ifbn    = sm + 13644;          // 2 x 64
    float* red_s   = sm + 13772;          // 8 slots x 10 (slot 7 stays 0)
    float* rdan_s  = sm + 13852;          // 20
    float* rbdan_s = sm + 13872;          // 20
    float* wro_s   = sm + 13892;          // 20
    float* wext_s  = sm + 13912;          // 120

    const int tid  = threadIdx.x;
    const int bx   = blockIdx.x;
    const int b    = bx >> 1;
    const int rank = bx & 1;
    const int prank = rank ^ 1;
    const int m_off = rank * 10;
    const int lane = tid & 31;
    const int warp = tid >> 5;
    const int g    = tid >> 8;
    const int q    = tid & 255;
    const bool owner = (q < 200);

    int ci2 = -1;
    bool is_loc = false, is_peer = false;
    if (warp == 7) {
        if (lane < 10)      { ci2 = m_off + lane;            is_loc  = true; }
        else if (lane < 20) { ci2 = (m_off ^ 10) + lane - 10; is_peer = true; }
        else                { ci2 = 20 + (lane - 20); }
    } else if (warp == 15) {
        if (lane < 24) ci2 = 32 + lane;
    } else if (warp == 6) {
        if (lane >= 8 && lane < 20) ci2 = 56 + (lane - 8);
    } else if (warp == 14) {
        if (lane >= 8 && lane < 20) ci2 = 68 + (lane - 8);
    }

    float* out_r  = out;
    float* out_W  = out + (long)TT * BB * NREC;
    float* out_wt = out_W + (long)TT * BB * NMBON * NKC;
    float* out_ro = out_wt + (long)TT * BB * NMBON * NKC;

    const float dt  = time_arr[1] - time_arr[0];
    const float a_r = dt;
    const float a_w = dt * 0.2f;

    const float* rkc_g = g_rkcT + (long)b * TT * NKC;

    const uint32_t imb_loc  = (uint32_t)__cvta_generic_to_shared(imb);
    const uint32_t mbar_loc = (uint32_t)__cvta_generic_to_shared(mbar_f);
    uint32_t imb_rem, mbar_rem;
    asm("mapa.shared::cluster.u32 %0, %1, %2;" : "=r"(imb_rem)  : "r"(imb_loc),  "r"(prank));
    asm("mapa.shared::cluster.u32 %0, %1, %2;" : "=r"(mbar_rem) : "r"(mbar_loc), "r"(prank));

    // ---------------- init ----------------
    if (tid == 0) {
        asm volatile("mbarrier.init.shared.b64 [%0], 14;" :: "r"(mbar_loc)     : "memory");
        asm volatile("mbarrier.init.shared.b64 [%0], 14;" :: "r"(mbar_loc + 8) : "memory");
    }
    for (int idx = tid; idx < NREC * NREC; idx += NTHREADS) {
        int i = idx / NREC, j = idx % NREC;
        float v = W_recur[idx];
        if (i < NMBON && j >= NREC - NDAN) v = 0.f;
        WrM[idx] = v;
    }
    if (tid < 80)       red_s[tid] = 0.f;
    if (tid < NREC)     bias_s[tid] = bias[tid];
    if (tid < NMBON)    wro_s[tid]  = W_readout[tid];
    if (tid >= 128 && tid < 128 + NFBN * 2) wext_s[tid - 128] = W_ext[tid - 128];
    if (tid < NREC) {
        float r0 = (tid < NMBON) ? 0.f : 0.1f;
        r_s[tid] = r0;
        if (rank == 0) out_r[(long)b * NREC + tid] = r0;
    }
    if (tid < NDAN) rbdan_s[tid] = 0.1f;
    for (int k = tid; k < NKC; k += NTHREADS)
        rkc4[k] = rkc_g[k];               // slot 0 = rkc(0)
    __syncthreads();                      // wext ready
    if (tid < NFBN) {
        float e0 = r_ext[((long)b * 2 + 0) * TT];
        float e1 = r_ext[((long)b * 2 + 1) * TT];
        ifbn[tid] = wext_s[tid * 2] * e0 + wext_s[tid * 2 + 1] * e1;
    }
    if (tid == 0 && rank == 0) out_ro[b] = 0.f;

    // owner state: W, wt, rb_kc (registers)
    float4 Wv[5], wtv[5], bkv;
    if (owner) {
        const long ibase = ((long)b * NMBON + m_off + g * 5) * NKC + q * 4;
        const long obase = ((long)b) * (NMBON * NKC) + (long)(m_off + g * 5) * NKC + q * 4;
#pragma unroll
        for (int mm = 0; mm < 5; ++mm) {
            float4 w  = *(const float4*)(W_kc0 + ibase + (long)mm * NKC);
            float4 wt = *(const float4*)(wt0   + ibase + (long)mm * NKC);
            Wv[mm] = w; wtv[mm] = wt;
            *(float4*)(out_W  + obase + (long)mm * NKC) = w;
            *(float4*)(out_wt + obase + (long)mm * NKC) = wt;
        }
        bkv = *(const float4*)(rkc_g + q * 4);   // rb_kc(-1) = rkc(:,0)
    } else {
#pragma unroll
        for (int mm = 0; mm < 5; ++mm) {
            Wv[mm]  = make_float4(0.f, 0.f, 0.f, 0.f);
            wtv[mm] = Wv[mm];
        }
        bkv = make_float4(0.f, 0.f, 0.f, 0.f);
    }

    // preloop prefetch: rkc(1) -> slot 1 (one committed group)
    if (warp == 15) {
        const float* gsrc = rkc_g + (long)1 * NKC;
#pragma unroll
        for (int j = 0; j < 7; ++j) {
            int c = lane + 32 * j;
            if (c < 200) {
                uint32_t dst = (uint32_t)__cvta_generic_to_shared(rkc4 + 800 + c * 4);
                asm volatile("cp.async.cg.shared.global [%0], [%1], 16;\n"
                             :: "r"(dst), "l"(gsrc + c * 4));
            }
        }
        asm volatile("cp.async.commit_group;\n" ::: "memory");
    }
    __syncthreads();
    asm volatile("barrier.cluster.arrive.aligned;" ::: "memory");
    asm volatile("barrier.cluster.wait.aligned;"   ::: "memory");

    // ---------------- time loop ----------------
    for (int t = 0; t < NSTEP; ++t) {
        const int s0  = t & 3;            // ring slot for rkc(t)
        const int hb  = t & 1;
        const int par = (t >> 1) & 1;

        const float* rc = r_s + hb * NREC;
        float* rn_buf   = r_s + (hb ^ 1) * NREC;

        // pre-bar1: B + EARLY SEND ∥ DAN-C (warp7) ∥ prefetch+ifbn+readout (warp15)
        if ((warp & 7) != 7) {
            float4 kc = make_float4(0.f, 0.f, 0.f, 0.f);
            if (owner) kc = *(const float4*)(rkc4 + s0 * 800 + q * 4);
            float pv[5];
#pragma unroll
            for (int mm = 0; mm < 5; ++mm) {
                float4 w = Wv[mm];
                float p = w.x * kc.x + w.y * kc.y + w.z * kc.z + w.w * kc.w;
                p += __shfl_xor_sync(0xffffffffu, p, 16);
                p += __shfl_xor_sync(0xffffffffu, p, 8);
                p += __shfl_xor_sync(0xffffffffu, p, 4);
                p += __shfl_xor_sync(0xffffffffu, p, 2);
                p += __shfl_xor_sync(0xffffffffu, p, 1);
                pv[mm] = p;
                if (lane == 0)
                    red_s[(warp & 7) * 10 + g * 5 + mm] = p;
            }
            // EARLY exchange: ship this warp's 5 partials to peer now
            if (lane == 0) {
                const uint32_t rbase = imb_rem + (hb * 70 + (warp & 7) * 10 + g * 5) * 4;
#pragma unroll
                for (int mm = 0; mm < 5; ++mm)
                    asm volatile("st.shared::cluster.f32 [%0], %1;"
                                 :: "r"(rbase + mm * 4), "f"(pv[mm]) : "memory");
                asm volatile("mbarrier.arrive.release.cluster.shared::cluster.b64 _, [%0];"
                             :: "r"(mbar_rem + hb * 8) : "memory");
            }
        } else if (warp == 7) {
            if (lane < NDAN) {
                const int i = 80 + lane;
                const float4* wrow = (const float4*)(WrM + i * NREC);
                const float4* r4   = (const float4*)rc;
                float a0 = 0.f, a1 = 0.f, a2 = 0.f, a3 = 0.f;
#pragma unroll
                for (int jb = 0; jb < 25; ++jb) {
                    float4 wv = wrow[jb];
                    float4 rv = r4[jb];
                    a0 = fmaf(wv.x, rv.x, a0);
                    a1 = fmaf(wv.y, rv.y, a1);
                    a2 = fmaf(wv.z, rv.z, a2);
                    a3 = fmaf(wv.w, rv.w, a3);
                }
                float pre  = (a0 + a1) + (a2 + a3) + bias_s[i];
                float relu = fmaxf(pre, 0.f);
                float rold = rc[i];
                float rn   = fmaf(a_r, relu - rold, rold);
                rn_buf[i] = rn;
                if (rank == 0) out_r[((long)(t + 1) * BB + b) * NREC + i] = rn;
                rdan_s[lane] = rn;
                float rb = rbdan_s[lane];
                rbdan_s[lane] = fmaf(a_w, rn - rb, rb);
            }
        } else {
            // warp 15: distance-2 prefetch rkc(t+2), ifbn(t+1), readout(t)
            if (t + 2 <= NSTEP - 1) {
                const float* gsrc = rkc_g + (long)(t + 2) * NKC;
                const int sw = (t + 2) & 3;
#pragma unroll
                for (int j = 0; j < 7; ++j) {
                    int c = lane + 32 * j;
                    if (c < 200) {
                        uint32_t dst = (uint32_t)__cvta_generic_to_shared(rkc4 + sw * 800 + c * 4);
                        asm volatile("cp.async.cg.shared.global [%0], [%1], 16;\n"
                                     :: "r"(dst), "l"(gsrc + c * 4));
                    }
                }
            }
            asm volatile("cp.async.commit_group;\n" ::: "memory");   // possibly empty
            float e0 = r_ext[((long)b * 2 + 0) * TT + (t + 1)];
            float e1 = r_ext[((long)b * 2 + 1) * TT + (t + 1)];
            {
                int f = lane;
                ifbn[(hb ^ 1) * 64 + f] = wext_s[f * 2] * e0 + wext_s[f * 2 + 1] * e1;
                f = lane + 32;
                if (f < NFBN)
                    ifbn[(hb ^ 1) * 64 + f] = wext_s[f * 2] * e0 + wext_s[f * 2 + 1] * e1;
            }
            if (lane == 24 && rank == 0) {
                // readout(t) from r(t) (t=0 recomputes the init value, = 0)
                float v = 0.f;
#pragma unroll
                for (int m = 0; m < NMBON; ++m)
                    v = fmaf(rc[m], wro_s[m], v);
                out_ro[(long)t * BB + b] = v;
            }
        }
        __syncthreads();   // bar1: red_s, rdan/rbdan(t), ifbn(t+1) ready

        // post-bar1: D (owners) ∥ C dots (exchange already in flight) ∥ cp wait
        if (owner) {
            // D(t): rb_kc EMA in registers + plasticity + streaming stores
            float4 kc = *(const float4*)(rkc4 + s0 * 800 + q * 4);
            bkv.x = fmaf(a_w, kc.x - bkv.x, bkv.x);
            bkv.y = fmaf(a_w, kc.y - bkv.y, bkv.y);
            bkv.z = fmaf(a_w, kc.z - bkv.z, bkv.z);
            bkv.w = fmaf(a_w, kc.w - bkv.w, bkv.w);
            const long obase = ((long)(t + 1) * BB + b) * (NMBON * NKC)
                             + (long)(m_off + g * 5) * NKC + q * 4;
#pragma unroll
            for (int mm = 0; mm < 5; ++mm) {
                const int m = m_off + g * 5 + mm;
                const float rbd = rbdan_s[m];
                const float rd  = rdan_s[m];
                float4 w = Wv[mm], wt = wtv[mm];
                float dw;
                dw = fmaf(rbd, kc.x, -(rd * bkv.x)); wt.x = fmaf(dw, dt, wt.x);
                dw = fmaf(rbd, kc.y, -(rd * bkv.y)); wt.y = fmaf(dw, dt, wt.y);
                dw = fmaf(rbd, kc.z, -(rd * bkv.z)); wt.z = fmaf(dw, dt, wt.z);
                dw = fmaf(rbd, kc.w, -(rd * bkv.w)); wt.w = fmaf(dw, dt, wt.w);
                w.x = fminf(fmaxf(fmaf(a_w, wt.x - w.x, w.x), 0.f), W_MAXC);
                w.y = fminf(fmaxf(fmaf(a_w, wt.y - w.y, w.y), 0.f), W_MAXC);
                w.z = fminf(fmaxf(fmaf(a_w, wt.z - w.z, w.z), 0.f), W_MAXC);
                w.w = fminf(fmaxf(fmaf(a_w, wt.w - w.w, w.w), 0.f), W_MAXC);
                Wv[mm] = w; wtv[mm] = wt;
                *(float4*)(out_W  + obase + (long)mm * NKC) = w;
                *(float4*)(out_wt + obase + (long)mm * NKC) = wt;
            }
        }

        if (ci2 >= 0) {
            const int i = ci2;
            const float4* wrow = (const float4*)(WrM + i * NREC);
            const float4* r4   = (const float4*)rc;
            float a0 = 0.f, a1 = 0.f, a2 = 0.f, a3 = 0.f;
#pragma unroll
            for (int jb = 0; jb < 25; ++jb) {
                float4 wv = wrow[jb];
                float4 rv = r4[jb];
                a0 = fmaf(wv.x, rv.x, a0);
                a1 = fmaf(wv.y, rv.y, a1);
                a2 = fmaf(wv.z, rv.z, a2);
                a3 = fmaf(wv.w, rv.w, a3);
            }
            float p = (a0 + a1) + (a2 + a3);
            float itot;
            if (is_loc) {
                // local rows: sum the 7 per-warp partials from red_s
                float s0l = red_s[0 * 10 + lane] + red_s[1 * 10 + lane];
                float s1l = red_s[2 * 10 + lane] + red_s[3 * 10 + lane];
                float s2l = red_s[4 * 10 + lane] + red_s[5 * 10 + lane];
                itot = (s0l + s1l) + (s2l + red_s[6 * 10 + lane]);
            } else if (is_peer) {
                uint32_t done;
                asm volatile(
                    "{\n\t.reg .pred p;\n\t"
                    "mbarrier.try_wait.parity.acquire.cluster.shared::cta.b64 p, [%1], %2;\n\t"
                    "selp.b32 %0, 1, 0, p;\n\t}"
                    : "=r"(done) : "r"(mbar_loc + hb * 8), "r"(par) : "memory");
                while (!done) {
                    asm volatile(
                        "{\n\t.reg .pred p;\n\t"
                        "mbarrier.try_wait.parity.acquire.cluster.shared::cta.b64 p, [%1], %2, 0x989680;\n\t"
                        "selp.b32 %0, 1, 0, p;\n\t}"
                        : "=r"(done) : "r"(mbar_loc + hb * 8), "r"(par) : "memory");
                }
                const int lr = lane - 10;
                float s0p = imb[hb * 70 + 0 * 10 + lr] + imb[hb * 70 + 1 * 10 + lr];
                float s1p = imb[hb * 70 + 2 * 10 + lr] + imb[hb * 70 + 3 * 10 + lr];
                float s2p = imb[hb * 70 + 4 * 10 + lr] + imb[hb * 70 + 5 * 10 + lr];
                itot = (s0p + s1p) + (s2p + imb[hb * 70 + 6 * 10 + lr]);
            } else {
                itot = ifbn[hb * 64 + (i - NMBON)];
            }
            float pre  = p + bias_s[i] + itot;
            float relu = fmaxf(pre, 0.f);
            float rold = rc[i];
            float rn   = fmaf(a_r, relu - rold, rold);
            rn_buf[i] = rn;
            if (rank == 0) out_r[((long)(t + 1) * BB + b) * NREC + i] = rn;
        }

        if (warp == 15)
            asm volatile("cp.async.wait_group 1;\n" ::: "memory");   // rkc(t+1) ready

        __syncthreads();   // bar2
    }

    // final readout: r(120) is in buffer 0
    if (warp == 15 && lane == 24 && rank == 0) {
        float v = 0.f;
#pragma unroll
        for (int m = 0; m < NMBON; ++m)
            v = fmaf(r_s[m], wro_s[m], v);
        out_ro[(long)NSTEP * BB + b] = v;
    }

    asm volatile("barrier.cluster.arrive.aligned;" ::: "memory");
    asm volatile("barrier.cluster.wait.aligned;"   ::: "memory");
}

// ---------------------------------------------------------------------------
extern "C" void kernel_launch(void* const* d_in, const int* in_sizes, int n_in,
                              void* d_out, int out_size) {
    const float* r_kc      = (const float*)d_in[0];
    const float* r_ext     = (const float*)d_in[1];
    const float* time_arr  = (const float*)d_in[2];
    const float* W_kc0     = (const float*)d_in[3];
    const float* wt0       = (const float*)d_in[4];
    const float* W_recur   = (const float*)d_in[5];
    const float* W_readout = (const float*)d_in[6];
    const float* bias      = (const float*)d_in[7];
    const float* W_ext     = (const float*)d_in[8];
    float* out = (float*)d_out;

    cudaFuncSetAttribute(rnn_kernel, cudaFuncAttributeMaxDynamicSharedMemorySize,
                         SM_FLOATS * (int)sizeof(float));

    transpose_kernel<<<dim3(4, 25, BB), dim3(32, 32)>>>(r_kc);
    rnn_kernel<<<NCTA, NTHREADS, SM_FLOATS * (int)sizeof(float)>>>(
        r_ext, time_arr, W_kc0, wt0, W_recur, W_readout, bias, W_ext, out);
}

// round 13
// speedup vs baseline: 1.2983x; 1.2983x over previous
#include <cuda_runtime.h>
#include <cstdint>

#define BB      48
#define NKC     800
#define NMBON   20
#define NFBN    60
#define NDAN    20
#define NREC    100
#define TT      121
#define NSTEP   120
#define W_MAXC  0.05f

#define NTHREADS 512
#define NCTA     (BB * 2)

__device__ float g_rkcT[(long)BB * TT * NKC];

// ---------------------------------------------------------------------------
// Transpose r_kc [B, NKC, T] -> g_rkcT [B, T, NKC]
// ---------------------------------------------------------------------------
__global__ void transpose_kernel(const float* __restrict__ rkc) {
    __shared__ float tile[32][33];
    const int bz = blockIdx.z;
    const int kt = blockIdx.y;
    const int tt = blockIdx.x;
    const int tx = threadIdx.x, ty = threadIdx.y;

    int k = kt * 32 + ty;
    int t = tt * 32 + tx;
    if (t < TT)
        tile[ty][tx] = rkc[((long)bz * NKC + k) * TT + t];
    __syncthreads();
    int t2 = tt * 32 + ty;
    int k2 = kt * 32 + tx;
    if (t2 < TT)
        g_rkcT[((long)bz * TT + t2) * NKC + k2] = tile[tx][ty];
}

// ---------------------------------------------------------------------------
// R11 (279us, best) + readout moved off owner warp 0 (post-bar2) to warp 15
// lane 24 (pre-bar1, reads r(t)). Everything else identical to R11.
// Cluster of 2 CTAs per batch (m-split), 512 threads.
// Warp 7: DAN-C pre-bar1; post-bar1 lanes 0-9 send+local-mbon, 10-19
//   peer-mbon (wait), 20-31 fbn 20-31.
// Warp 15: cp.async prefetch (distance 2) + ifbn + readout pre-bar1;
//   lanes 0-23 fbn dots 32-55 post-bar1 + wait_group 1.
// Warp 6 lanes 8-19: fbn 56-67. Warp 14 lanes 8-19: fbn 68-79.
// ---------------------------------------------------------------------------
// smem floats: mbar 4 | imb 40 | WrM 10000 | rkc4 3200 | r 200 | bias 100 |
//              ifbn 128 | red 80 | rdan 20 | rbdan 20 | wro 20 | wext 120
#define SM_FLOATS (4 + 40 + 10000 + 3200 + 200 + 100 + 128 + 80 + 20 + 20 + 20 + 120)

__global__ __launch_bounds__(NTHREADS, 1) __cluster_dims__(2, 1, 1)
void rnn_kernel(
    const float* __restrict__ r_ext,
    const float* __restrict__ time_arr,
    const float* __restrict__ W_kc0,
    const float* __restrict__ wt0,
    const float* __restrict__ W_recur,
    const float* __restrict__ W_readout,
    const float* __restrict__ bias,
    const float* __restrict__ W_ext,
    float* __restrict__ out)
{
    extern __shared__ float sm[];
    float* mbar_f  = sm;                  // 4
    float* imb     = sm + 4;              // 2 x 20
    float* WrM     = sm + 44;             // 100 x 100 row-major
    float* rkc4    = sm + 10044;          // 4 x 800 ring
    float* r_s     = sm + 13244;          // 2 x 100
    float* bias_s  = sm + 13444;          // 100
    float* ifbn    = sm + 13544;          // 2 x 64
    float* red_s   = sm + 13672;          // 8 slots x 10 (slot 7 stays 0)
    float* rdan_s  = sm + 13752;          // 20
    float* rbdan_s = sm + 13772;          // 20
    float* wro_s   = sm + 13792;          // 20
    float* wext_s  = sm + 13812;          // 120

    const int tid  = threadIdx.x;
    const int bx   = blockIdx.x;
    const int b    = bx >> 1;
    const int rank = bx & 1;
    const int prank = rank ^ 1;
    const int m_off = rank * 10;
    const int lane = tid & 31;
    const int warp = tid >> 5;
    const int g    = tid >> 8;
    const int q    = tid & 255;
    const bool owner = (q < 200);

    int ci2 = -1;
    bool is_loc = false, is_peer = false;
    if (warp == 7) {
        if (lane < 10)      { ci2 = m_off + lane;            is_loc  = true; }
        else if (lane < 20) { ci2 = (m_off ^ 10) + lane - 10; is_peer = true; }
        else                { ci2 = 20 + (lane - 20); }
    } else if (warp == 15) {
        if (lane < 24) ci2 = 32 + lane;
    } else if (warp == 6) {
        if (lane >= 8 && lane < 20) ci2 = 56 + (lane - 8);
    } else if (warp == 14) {
        if (lane >= 8 && lane < 20) ci2 = 68 + (lane - 8);
    }

    float* out_r  = out;
    float* out_W  = out + (long)TT * BB * NREC;
    float* out_wt = out_W + (long)TT * BB * NMBON * NKC;
    float* out_ro = out_wt + (long)TT * BB * NMBON * NKC;

    const float dt  = time_arr[1] - time_arr[0];
    const float a_r = dt;
    const float a_w = dt * 0.2f;

    const float* rkc_g = g_rkcT + (long)b * TT * NKC;

    const uint32_t imb_loc  = (uint32_t)__cvta_generic_to_shared(imb);
    const uint32_t mbar_loc = (uint32_t)__cvta_generic_to_shared(mbar_f);
    uint32_t imb_rem, mbar_rem;
    asm("mapa.shared::cluster.u32 %0, %1, %2;" : "=r"(imb_rem)  : "r"(imb_loc),  "r"(prank));
    asm("mapa.shared::cluster.u32 %0, %1, %2;" : "=r"(mbar_rem) : "r"(mbar_loc), "r"(prank));

    // ---------------- init ----------------
    if (tid == 0) {
        asm volatile("mbarrier.init.shared.b64 [%0], 10;" :: "r"(mbar_loc)     : "memory");
        asm volatile("mbarrier.init.shared.b64 [%0], 10;" :: "r"(mbar_loc + 8) : "memory");
    }
    for (int idx = tid; idx < NREC * NREC; idx += NTHREADS) {
        int i = idx / NREC, j = idx % NREC;
        float v = W_recur[idx];
        if (i < NMBON && j >= NREC - NDAN) v = 0.f;
        WrM[idx] = v;
    }
    if (tid < 80)       red_s[tid] = 0.f;
    if (tid < NREC)     bias_s[tid] = bias[tid];
    if (tid < NMBON)    wro_s[tid]  = W_readout[tid];
    if (tid >= 128 && tid < 128 + NFBN * 2) wext_s[tid - 128] = W_ext[tid - 128];
    if (tid < NREC) {
        float r0 = (tid < NMBON) ? 0.f : 0.1f;
        r_s[tid] = r0;
        if (rank == 0) out_r[(long)b * NREC + tid] = r0;
    }
    if (tid < NDAN) rbdan_s[tid] = 0.1f;
    for (int k = tid; k < NKC; k += NTHREADS)
        rkc4[k] = rkc_g[k];               // slot 0 = rkc(0)
    __syncthreads();                      // wext ready
    if (tid < NFBN) {
        float e0 = r_ext[((long)b * 2 + 0) * TT];
        float e1 = r_ext[((long)b * 2 + 1) * TT];
        ifbn[tid] = wext_s[tid * 2] * e0 + wext_s[tid * 2 + 1] * e1;
    }
    if (tid == 0 && rank == 0) out_ro[b] = 0.f;

    // owner state: W, wt, rb_kc (registers)
    float4 Wv[5], wtv[5], bkv;
    if (owner) {
        const long ibase = ((long)b * NMBON + m_off + g * 5) * NKC + q * 4;
        const long obase = ((long)b) * (NMBON * NKC) + (long)(m_off + g * 5) * NKC + q * 4;
#pragma unroll
        for (int mm = 0; mm < 5; ++mm) {
            float4 w  = *(const float4*)(W_kc0 + ibase + (long)mm * NKC);
            float4 wt = *(const float4*)(wt0   + ibase + (long)mm * NKC);
            Wv[mm] = w; wtv[mm] = wt;
            *(float4*)(out_W  + obase + (long)mm * NKC) = w;
            *(float4*)(out_wt + obase + (long)mm * NKC) = wt;
        }
        bkv = *(const float4*)(rkc_g + q * 4);   // rb_kc(-1) = rkc(:,0)
    } else {
#pragma unroll
        for (int mm = 0; mm < 5; ++mm) {
            Wv[mm]  = make_float4(0.f, 0.f, 0.f, 0.f);
            wtv[mm] = Wv[mm];
        }
        bkv = make_float4(0.f, 0.f, 0.f, 0.f);
    }

    // preloop prefetch: rkc(1) -> slot 1 (one committed group)
    if (warp == 15) {
        const float* gsrc = rkc_g + (long)1 * NKC;
#pragma unroll
        for (int j = 0; j < 7; ++j) {
            int c = lane + 32 * j;
            if (c < 200) {
                uint32_t dst = (uint32_t)__cvta_generic_to_shared(rkc4 + 800 + c * 4);
                asm volatile("cp.async.cg.shared.global [%0], [%1], 16;\n"
                             :: "r"(dst), "l"(gsrc + c * 4));
            }
        }
        asm volatile("cp.async.commit_group;\n" ::: "memory");
    }
    __syncthreads();
    asm volatile("barrier.cluster.arrive.aligned;" ::: "memory");
    asm volatile("barrier.cluster.wait.aligned;"   ::: "memory");

    // ---------------- time loop ----------------
    for (int t = 0; t < NSTEP; ++t) {
        const int s0  = t & 3;            // ring slot for rkc(t)
        const int hb  = t & 1;
        const int par = (t >> 1) & 1;

        const float* rc = r_s + hb * NREC;
        float* rn_buf   = r_s + (hb ^ 1) * NREC;

        // pre-bar1: B ∥ DAN-C (warp7) ∥ prefetch+ifbn+readout (warp15)
        if ((warp & 7) != 7) {
            float4 kc = make_float4(0.f, 0.f, 0.f, 0.f);
            if (owner) kc = *(const float4*)(rkc4 + s0 * 800 + q * 4);
#pragma unroll
            for (int mm = 0; mm < 5; ++mm) {
                float4 w = Wv[mm];
                float p = w.x * kc.x + w.y * kc.y + w.z * kc.z + w.w * kc.w;
                p += __shfl_xor_sync(0xffffffffu, p, 16);
                p += __shfl_xor_sync(0xffffffffu, p, 8);
                p += __shfl_xor_sync(0xffffffffu, p, 4);
                p += __shfl_xor_sync(0xffffffffu, p, 2);
                p += __shfl_xor_sync(0xffffffffu, p, 1);
                if (lane == 0)
                    red_s[(warp & 7) * 10 + g * 5 + mm] = p;
            }
        } else if (warp == 7) {
            if (lane < NDAN) {
                const int i = 80 + lane;
                const float4* wrow = (const float4*)(WrM + i * NREC);
                const float4* r4   = (const float4*)rc;
                float a0 = 0.f, a1 = 0.f, a2 = 0.f, a3 = 0.f;
#pragma unroll
                for (int jb = 0; jb < 25; ++jb) {
                    float4 wv = wrow[jb];
                    float4 rv = r4[jb];
                    a0 = fmaf(wv.x, rv.x, a0);
                    a1 = fmaf(wv.y, rv.y, a1);
                    a2 = fmaf(wv.z, rv.z, a2);
                    a3 = fmaf(wv.w, rv.w, a3);
                }
                float pre  = (a0 + a1) + (a2 + a3) + bias_s[i];
                float relu = fmaxf(pre, 0.f);
                float rold = rc[i];
                float rn   = fmaf(a_r, relu - rold, rold);
                rn_buf[i] = rn;
                if (rank == 0) out_r[((long)(t + 1) * BB + b) * NREC + i] = rn;
                rdan_s[lane] = rn;
                float rb = rbdan_s[lane];
                rbdan_s[lane] = fmaf(a_w, rn - rb, rb);
            }
        } else {
            // warp 15: distance-2 prefetch rkc(t+2), ifbn(t+1), readout(t)
            if (t + 2 <= NSTEP - 1) {
                const float* gsrc = rkc_g + (long)(t + 2) * NKC;
                const int sw = (t + 2) & 3;
#pragma unroll
                for (int j = 0; j < 7; ++j) {
                    int c = lane + 32 * j;
                    if (c < 200) {
                        uint32_t dst = (uint32_t)__cvta_generic_to_shared(rkc4 + sw * 800 + c * 4);
                        asm volatile("cp.async.cg.shared.global [%0], [%1], 16;\n"
                                     :: "r"(dst), "l"(gsrc + c * 4));
                    }
                }
            }
            asm volatile("cp.async.commit_group;\n" ::: "memory");   // possibly empty
            float e0 = r_ext[((long)b * 2 + 0) * TT + (t + 1)];
            float e1 = r_ext[((long)b * 2 + 1) * TT + (t + 1)];
            {
                int f = lane;
                ifbn[(hb ^ 1) * 64 + f] = wext_s[f * 2] * e0 + wext_s[f * 2 + 1] * e1;
                f = lane + 32;
                if (f < NFBN)
                    ifbn[(hb ^ 1) * 64 + f] = wext_s[f * 2] * e0 + wext_s[f * 2 + 1] * e1;
            }
            if (lane == 24 && rank == 0 && t > 0) {
                // readout(t) from r(t); out_ro[0] written in init (= 0)
                float v = 0.f;
#pragma unroll
                for (int m = 0; m < NMBON; ++m)
                    v = fmaf(rc[m], wro_s[m], v);
                out_ro[(long)t * BB + b] = v;
            }
        }
        __syncthreads();   // bar1: red_s, rdan/rbdan(t), ifbn(t+1) ready

        // post-bar1: send FIRST, then D (owners) ∥ C dots ∥ cp wait
        float vloc = 0.f;
        if (warp == 7 && lane < 10) {
            vloc = red_s[0 * 10 + lane] + red_s[1 * 10 + lane] + red_s[2 * 10 + lane]
                 + red_s[3 * 10 + lane] + red_s[4 * 10 + lane] + red_s[5 * 10 + lane]
                 + red_s[6 * 10 + lane];
            asm volatile("st.shared::cluster.f32 [%0], %1;"
                         :: "r"(imb_rem + (hb * 20 + m_off + lane) * 4), "f"(vloc) : "memory");
            asm volatile("mbarrier.arrive.release.cluster.shared::cluster.b64 _, [%0];"
                         :: "r"(mbar_rem + hb * 8) : "memory");
        }

        if (owner) {
            // D(t): rb_kc EMA in registers + plasticity + streaming stores
            float4 kc = *(const float4*)(rkc4 + s0 * 800 + q * 4);
            bkv.x = fmaf(a_w, kc.x - bkv.x, bkv.x);
            bkv.y = fmaf(a_w, kc.y - bkv.y, bkv.y);
            bkv.z = fmaf(a_w, kc.z - bkv.z, bkv.z);
            bkv.w = fmaf(a_w, kc.w - bkv.w, bkv.w);
            const long obase = ((long)(t + 1) * BB + b) * (NMBON * NKC)
                             + (long)(m_off + g * 5) * NKC + q * 4;
#pragma unroll
            for (int mm = 0; mm < 5; ++mm) {
                const int m = m_off + g * 5 + mm;
                const float rbd = rbdan_s[m];
                const float rd  = rdan_s[m];
                float4 w = Wv[mm], wt = wtv[mm];
                float dw;
                dw = fmaf(rbd, kc.x, -(rd * bkv.x)); wt.x = fmaf(dw, dt, wt.x);
                dw = fmaf(rbd, kc.y, -(rd * bkv.y)); wt.y = fmaf(dw, dt, wt.y);
                dw = fmaf(rbd, kc.z, -(rd * bkv.z)); wt.z = fmaf(dw, dt, wt.z);
                dw = fmaf(rbd, kc.w, -(rd * bkv.w)); wt.w = fmaf(dw, dt, wt.w);
                w.x = fminf(fmaxf(fmaf(a_w, wt.x - w.x, w.x), 0.f), W_MAXC);
                w.y = fminf(fmaxf(fmaf(a_w, wt.y - w.y, w.y), 0.f), W_MAXC);
                w.z = fminf(fmaxf(fmaf(a_w, wt.z - w.z, w.z), 0.f), W_MAXC);
                w.w = fminf(fmaxf(fmaf(a_w, wt.w - w.w, w.w), 0.f), W_MAXC);
                Wv[mm] = w; wtv[mm] = wt;
                *(float4*)(out_W  + obase + (long)mm * NKC) = w;
                *(float4*)(out_wt + obase + (long)mm * NKC) = wt;
            }
        }

        if (ci2 >= 0) {
            const int i = ci2;
            const float4* wrow = (const float4*)(WrM + i * NREC);
            const float4* r4   = (const float4*)rc;
            float a0 = 0.f, a1 = 0.f, a2 = 0.f, a3 = 0.f;
#pragma unroll
            for (int jb = 0; jb < 25; ++jb) {
                float4 wv = wrow[jb];
                float4 rv = r4[jb];
                a0 = fmaf(wv.x, rv.x, a0);
                a1 = fmaf(wv.y, rv.y, a1);
                a2 = fmaf(wv.z, rv.z, a2);
                a3 = fmaf(wv.w, rv.w, a3);
            }
            float p = (a0 + a1) + (a2 + a3);
            float itot;
            if (is_loc) {
                itot = vloc;
            } else if (is_peer) {
                uint32_t done;
                asm volatile(
                    "{\n\t.reg .pred p;\n\t"
                    "mbarrier.try_wait.parity.acquire.cluster.shared::cta.b64 p, [%1], %2;\n\t"
                    "selp.b32 %0, 1, 0, p;\n\t}"
                    : "=r"(done) : "r"(mbar_loc + hb * 8), "r"(par) : "memory");
                while (!done) {
                    asm volatile(
                        "{\n\t.reg .pred p;\n\t"
                        "mbarrier.try_wait.parity.acquire.cluster.shared::cta.b64 p, [%1], %2, 0x989680;\n\t"
                        "selp.b32 %0, 1, 0, p;\n\t}"
                        : "=r"(done) : "r"(mbar_loc + hb * 8), "r"(par) : "memory");
                }
                itot = imb[hb * 20 + i];
            } else {
                itot = ifbn[hb * 64 + (i - NMBON)];
            }
            float pre  = p + bias_s[i] + itot;
            float relu = fmaxf(pre, 0.f);
            float rold = rc[i];
            float rn   = fmaf(a_r, relu - rold, rold);
            rn_buf[i] = rn;
            if (rank == 0) out_r[((long)(t + 1) * BB + b) * NREC + i] = rn;
        }

        if (warp == 15)
            asm volatile("cp.async.wait_group 1;\n" ::: "memory");   // rkc(t+1) ready

        __syncthreads();   // bar2
    }

    // final readout: r(120) is in buffer 0
    if (warp == 15 && lane == 24 && rank == 0) {
        float v = 0.f;
#pragma unroll
        for (int m = 0; m < NMBON; ++m)
            v = fmaf(r_s[m], wro_s[m], v);
        out_ro[(long)NSTEP * BB + b] = v;
    }

    asm volatile("barrier.cluster.arrive.aligned;" ::: "memory");
    asm volatile("barrier.cluster.wait.aligned;"   ::: "memory");
}

// ---------------------------------------------------------------------------
extern "C" void kernel_launch(void* const* d_in, const int* in_sizes, int n_in,
                              void* d_out, int out_size) {
    const float* r_kc      = (const float*)d_in[0];
    const float* r_ext     = (const float*)d_in[1];
    const float* time_arr  = (const float*)d_in[2];
    const float* W_kc0     = (const float*)d_in[3];
    const float* wt0       = (const float*)d_in[4];
    const float* W_recur   = (const float*)d_in[5];
    const float* W_readout = (const float*)d_in[6];
    const float* bias      = (const float*)d_in[7];
    const float* W_ext     = (const float*)d_in[8];
    float* out = (float*)d_out;

    cudaFuncSetAttribute(rnn_kernel, cudaFuncAttributeMaxDynamicSharedMemorySize,
                         SM_FLOATS * (int)sizeof(float));

    transpose_kernel<<<dim3(4, 25, BB), dim3(32, 32)>>>(r_kc);
    rnn_kernel<<<NCTA, NTHREADS, SM_FLOATS * (int)sizeof(float)>>>(
        r_ext, time_arr, W_kc0, wt0, W_recur, W_readout, bias, W_ext, out);
}